// round 12
// baseline (speedup 1.0000x reference)
#include <cuda_runtime.h>
#include <cuda_fp16.h>
#include <cstdint>

#define T 256
#define H 128
#define V 60
#define M 4            // batch rows per CTA
#define NT 256
#define NCTA 256       // 2 CTAs per SM
#define PSW 132        // padded proj row stride

typedef unsigned long long u64;

__device__ __align__(16) float g_proj[V * H];

__device__ __forceinline__ float fast_tanh(float x) {
    float e = __expf(2.0f * x);
    return 1.0f - __fdividef(2.0f, e + 1.0f);
}
__device__ __forceinline__ void mma_f16(float* c, const uint32_t* a,
                                        uint32_t b0, uint32_t b1) {
    asm volatile(
        "mma.sync.aligned.m16n8k16.row.col.f32.f16.f16.f32 "
        "{%0,%1,%2,%3}, {%4,%5,%6,%7}, {%8,%9}, {%0,%1,%2,%3};"
        : "+f"(c[0]), "+f"(c[1]), "+f"(c[2]), "+f"(c[3])
        : "r"(a[0]), "r"(a[1]), "r"(a[2]), "r"(a[3]), "r"(b0), "r"(b1));
}
__device__ __forceinline__ uint32_t split_pack(float2 v, uint32_t& lo) {
    __half h0 = __float2half_rn(v.x), h1 = __float2half_rn(v.y);
    __half l0 = __float2half_rn(v.x - __half2float(h0));
    __half l1 = __float2half_rn(v.y - __half2float(h1));
    lo = ((uint32_t)__half_as_ushort(l1) << 16) | __half_as_ushort(l0);
    return ((uint32_t)__half_as_ushort(h1) << 16) | __half_as_ushort(h0);
}
__device__ __forceinline__ void split1(float h, unsigned short& hi, unsigned short& lo) {
    __half hh = __float2half_rn(h);
    __half ll = __float2half_rn(h - __half2float(hh));
    hi = __half_as_ushort(hh);
    lo = __half_as_ushort(ll);
}

// B tile: per kt (k-tile of 16), granule (kq, n) = 8 bytes holding halves
// k = {2kq, 2kq+1, 2kq+8, 2kq+9} of logical column n (n = 2m + split).
// byte addr = kt*256 + kq*64 + (n ^ kq)*8.  Load: lane (g=l>>2, c=l&3)
// reads (kq=c, n=g) -> one LDS.64 = {b0, b1} for mma.
__device__ __forceinline__ void store_h(float* Bn, int w, int g, int c,
                                        float h1, float h2) {
    char* bb = (char*)Bn;
    const int q = g >> 1;
    const int pr = (g & 1) * 2;
    char* base = bb + w * 256 + q * 64;
    unsigned short h1h, h1l, h2h, h2l;
    split1(h1, h1h, h1l);
    split1(h2, h2h, h2l);
    char* ghi = base + (((2 * c) ^ q) << 3);      // col 2c   (hi)
    char* glo = base + (((2 * c + 1) ^ q) << 3);  // col 2c+1 (lo)
    *(unsigned short*)(ghi + pr)     = h1h;       // j1 -> slot g&1
    *(unsigned short*)(ghi + 4 + pr) = h2h;       // j2 -> slot 2+(g&1)
    *(unsigned short*)(glo + pr)     = h1l;
    *(unsigned short*)(glo + 4 + pr) = h2l;
}

// ---------------------------------------------------------------------------
// Stage 1: proj[v][j] = emb[v] . W_ih[j]
// ---------------------------------------------------------------------------
__global__ void proj_kernel(const float* __restrict__ emb,
                            const float* __restrict__ W_ih) {
    __shared__ float e[H];
    const int v = blockIdx.x;
    const int j = threadIdx.x;
    e[j] = emb[v * H + j];
    __syncthreads();
    const float* w = W_ih + j * H;
    float s = 0.f;
#pragma unroll 16
    for (int k = 0; k < H; ++k) s += e[k] * w[k];
    g_proj[v * H + j] = s;
}

// ---------------------------------------------------------------------------
// Stage 2: persistent recurrence, fp16-split mma m16n8k16.
// B cols carry (m, split) pairs: col 2m = h_hi, col 2m+1 = h_lo, so only
// 2 MMAs per k-tile (A=Whi covers hi*hhi and hi*hlo; A=Wlo covers lo*hhi).
// Thread (g, c): j1 = 16w+g, j2 = j1+8, m = c. 2 CTAs/SM.
// ---------------------------------------------------------------------------
__global__ __launch_bounds__(NT, 2)
void rnn_kernel(const int* __restrict__ x,
                const int* __restrict__ lengths,
                const float* __restrict__ W_hh,
                const float* __restrict__ W_fc,
                const float* __restrict__ b_fc,
                float* __restrict__ out) {
    extern __shared__ float sm[];
    float* B0 = sm;                    // 512 floats (2048 B): h tile buf 0
    float* B1 = B0 + 512;              // 512 floats: h tile buf 1
    float* Ps = B1 + 512;              // V*PSW proj (reused for W_fc)
    float* Ls = Ps + V * PSW;          // M*H last hidden
    int*   Tok = (int*)(Ls + M * H);   // M*T tokens

    const int tid = threadIdx.x;
    const int w = tid >> 5, l = tid & 31;
    const int b0 = blockIdx.x * M;

    for (int idx = tid; idx < V * H; idx += NT) {
        int v = idx >> 7, j = idx & 127;
        Ps[v * PSW + j] = g_proj[idx];
    }
    for (int idx = tid; idx < M * T; idx += NT)
        Tok[idx] = x[b0 * T + idx];

    const int g = l >> 2, c = l & 3;
    const int j1 = w * 16 + g;
    const int j2 = j1 + 8;

    // --- W_hh fragments (fp16 hi/lo), m16n8k16 A layout (same as verified) ---
    uint32_t Ahi[8][4], Alo[8][4];
#pragma unroll
    for (int kt = 0; kt < 8; ++kt) {
        float2 wa = *(const float2*)&W_hh[j1 * H + kt * 16 + 2 * c];
        float2 wb = *(const float2*)&W_hh[j2 * H + kt * 16 + 2 * c];
        float2 wc = *(const float2*)&W_hh[j1 * H + kt * 16 + 8 + 2 * c];
        float2 wd = *(const float2*)&W_hh[j2 * H + kt * 16 + 8 + 2 * c];
        Ahi[kt][0] = split_pack(wa, Alo[kt][0]);
        Ahi[kt][1] = split_pack(wb, Alo[kt][1]);
        Ahi[kt][2] = split_pack(wc, Alo[kt][2]);
        Ahi[kt][3] = split_pack(wd, Alo[kt][3]);
    }

    const int len = lengths[b0 + c];
    __syncthreads();

    // --- peel step 0: h1 = tanh(proj[x_0]) ---
    {
        int tk = Tok[c * T];
        float h1 = fast_tanh(Ps[tk * PSW + j1]);
        float h2 = fast_tanh(Ps[tk * PSW + j2]);
        if (len == 1) { Ls[c * H + j1] = h1; Ls[c * H + j2] = h2; }
        store_h(B0, w, g, c, h1, h2);
    }
    __syncthreads();

    const int ldo = c * 64 + (g ^ c) * 8;   // per-lane load byte offset within kt block

    for (int i = 1; i < T; ++i) {
        const char* Bc = (const char*)((i & 1) ? B0 : B1);
        float*      Bn = (i & 1) ? B1 : B0;

        // prefetch token + proj adds (hidden under MMA)
        int tk = Tok[c * T + i];
        float p1 = Ps[tk * PSW + j1];
        float p2 = Ps[tk * PSW + j2];

        float accH[2][4], accL[2][4];
#pragma unroll
        for (int p = 0; p < 2; ++p)
#pragma unroll
            for (int e = 0; e < 4; ++e) { accH[p][e] = 0.f; accL[p][e] = 0.f; }

#pragma unroll
        for (int kt = 0; kt < 8; ++kt) {
            const int p = kt & 1;
            uint2 bb = *(const uint2*)(Bc + kt * 256 + ldo);
            mma_f16(accH[p], Ahi[kt], bb.x, bb.y);
            mma_f16(accL[p], Alo[kt], bb.x, bb.y);
        }

        // z = Whi*hhi + Whi*hlo + Wlo*hhi  (cols 2c, 2c+1, 2c of C)
        float z1 = ((accH[0][0] + accH[1][0]) + (accH[0][1] + accH[1][1]))
                 + (accL[0][0] + accL[1][0]) + p1;
        float z2 = ((accH[0][2] + accH[1][2]) + (accH[0][3] + accH[1][3]))
                 + (accL[0][2] + accL[1][2]) + p2;
        float h1 = fast_tanh(z1);
        float h2 = fast_tanh(z2);

        if (i == len - 1) { Ls[c * H + j1] = h1; Ls[c * H + j2] = h2; }
        store_h(Bn, w, g, c, h1, h2);
        __syncthreads();
    }

    // --- FC epilogue: out[b] = Ls[b] @ W_fc^T + b_fc (reuse Ps for W_fc) ---
    for (int idx = tid; idx < V * H; idx += NT) {
        int v = idx >> 7, j = idx & 127;
        Ps[v * PSW + j] = W_fc[idx];
    }
    __syncthreads();

    for (int p = tid; p < M * V; p += NT) {
        const int m = p / V, v = p % V;
        const float* lr = Ls + m * H;
        const float* wr = Ps + v * PSW;
        float s = b_fc[v];
#pragma unroll 8
        for (int k = 0; k < H; ++k) s += lr[k] * wr[k];
        out[(b0 + m) * V + v] = s;
    }
}

extern "C" void kernel_launch(void* const* d_in, const int* in_sizes, int n_in,
                              void* d_out, int out_size) {
    const int*   x       = (const int*)d_in[0];
    const int*   lengths = (const int*)d_in[1];
    const float* emb     = (const float*)d_in[2];
    const float* W_ih    = (const float*)d_in[3];
    const float* W_hh    = (const float*)d_in[4];
    const float* W_fc    = (const float*)d_in[5];
    const float* b_fc    = (const float*)d_in[6];
    float*       out     = (float*)d_out;

    proj_kernel<<<V, H>>>(emb, W_ih);

    size_t smem = (size_t)(2 * 512 + V * PSW + M * H) * sizeof(float)
                + (size_t)(M * T) * sizeof(int);
    cudaFuncSetAttribute(rnn_kernel, cudaFuncAttributeMaxDynamicSharedMemorySize,
                         (int)smem);
    rnn_kernel<<<NCTA, NT, smem>>>(x, lengths, W_hh, W_fc, b_fc, out);
}

// round 13
// speedup vs baseline: 1.0510x; 1.0510x over previous
#include <cuda_runtime.h>
#include <cuda_fp16.h>
#include <cstdint>

#define T 256
#define H 128
#define V 60
#define M 8
#define NT 256
#define NCTA 128
#define PSW 132

// ---- shared-memory word offsets --------------------------------------------
// main fp16-hi B tile: per buffer 512 words = [half(j<8 / j>=8)][kt][32 words]
//   word = half*256 + kt*32 + c*8 + (n ^ c), word = f16x2 of k {2c, 2c+1}, col n
// fp8 tiles (hlo*4096 and h): per buffer 256 words = [half(k32>=16)][q][32]
//   word = half*128 + q*32 + c*8 + (n ^ c), word = e4m3 x4 of k {4c..4c+3}, col n
#define MAIN_OFF(s) ((s) * 512)
#define FLO_OFF(s)  (1024 + (s) * 256)
#define FH_OFF(s)   (1536 + (s) * 256)
#define PS_OFF      2048
#define LS_OFF      (PS_OFF + V * PSW)
#define TOK_OFF     (LS_OFF + M * H)
#define SMWORDS     (TOK_OFF + M * T)

__device__ __align__(16) float g_proj[V * H];

__device__ __forceinline__ float fast_tanh(float x) {
    float e = __expf(2.0f * x);
    return 1.0f - __fdividef(2.0f, e + 1.0f);
}
__device__ __forceinline__ void mma_f16(float* c, const uint32_t* a,
                                        uint32_t b0, uint32_t b1) {
    asm volatile(
        "mma.sync.aligned.m16n8k16.row.col.f32.f16.f16.f32 "
        "{%0,%1,%2,%3}, {%4,%5,%6,%7}, {%8,%9}, {%0,%1,%2,%3};"
        : "+f"(c[0]), "+f"(c[1]), "+f"(c[2]), "+f"(c[3])
        : "r"(a[0]), "r"(a[1]), "r"(a[2]), "r"(a[3]), "r"(b0), "r"(b1));
}
__device__ __forceinline__ void mma_fp8(float* c, const uint32_t* a,
                                        uint32_t b0, uint32_t b1) {
    asm volatile(
        "mma.sync.aligned.m16n8k32.row.col.f32.e4m3.e4m3.f32 "
        "{%0,%1,%2,%3}, {%4,%5,%6,%7}, {%8,%9}, {%0,%1,%2,%3};"
        : "+f"(c[0]), "+f"(c[1]), "+f"(c[2]), "+f"(c[3])
        : "r"(a[0]), "r"(a[1]), "r"(a[2]), "r"(a[3]), "r"(b0), "r"(b1));
}
// pack 2 floats -> e4m3x2 (low byte = x0)
__device__ __forceinline__ uint16_t e4m3x2(float x1, float x0) {
    uint16_t r;
    asm("cvt.rn.satfinite.e4m3x2.f32 %0, %1, %2;" : "=h"(r) : "f"(x1), "f"(x0));
    return r;
}
__device__ __forceinline__ uint32_t pack_e4m3_4(float x0, float x1, float x2, float x3) {
    uint16_t lo = e4m3x2(x1, x0);
    uint16_t hi = e4m3x2(x3, x2);
    return ((uint32_t)hi << 16) | lo;
}
__device__ __forceinline__ uint32_t pack_f16(float a, float b) {  // low = a
    __half2 h = __floats2half2_rn(a, b);
    return *(uint32_t*)&h;
}

// ---------------------------------------------------------------------------
// Stage 1: proj[v][j] = emb[v] . W_ih[j]
// ---------------------------------------------------------------------------
__global__ void proj_kernel(const float* __restrict__ emb,
                            const float* __restrict__ W_ih) {
    __shared__ float e[H];
    const int v = blockIdx.x;
    const int j = threadIdx.x;
    e[j] = emb[v * H + j];
    __syncthreads();
    const float* w = W_ih + j * H;
    float s = 0.f;
#pragma unroll 16
    for (int k = 0; k < H; ++k) s += e[k] * w[k];
    g_proj[v * H + j] = s;
}

// ---------------------------------------------------------------------------
// Stage 2: persistent recurrence. Main term fp16 m16n8k16 (8 MMA),
// corrections fp8 e4m3 m16n8k32 (8 MMA). W fragments in registers.
// ---------------------------------------------------------------------------
__global__ __launch_bounds__(NT, 1)
void rnn_kernel(const int* __restrict__ x,
                const int* __restrict__ lengths,
                const float* __restrict__ W_hh,
                const float* __restrict__ W_fc,
                const float* __restrict__ b_fc,
                float* __restrict__ out) {
    extern __shared__ float sm[];
    float* Ps  = sm + PS_OFF;
    float* Ls  = sm + LS_OFF;
    int*   Tok = (int*)(sm + TOK_OFF);

    const int tid = threadIdx.x;
    const int w = tid >> 5, l = tid & 31;
    const int b0 = blockIdx.x * M;

    for (int idx = tid; idx < V * H; idx += NT) {
        int v = idx >> 7, j = idx & 127;
        Ps[v * PSW + j] = g_proj[idx];
    }
    for (int idx = tid; idx < M * T; idx += NT)
        Tok[idx] = x[b0 * T + idx];

    const int g = l >> 2, c = l & 3;
    const int j1 = w * 16 + g;
    const int j2 = j1 + 8;
    const int mA = 2 * c, mB = 2 * c + 1;

    // --- A fragments -------------------------------------------------------
    // fp16 main: a0=(j1, k 2c,2c+1), a1=(j2,..), a2=(j1, +8), a3=(j2, +8)
    uint32_t Af[8][4];
#pragma unroll
    for (int kt = 0; kt < 8; ++kt) {
        const float* r1 = W_hh + j1 * H + kt * 16;
        const float* r2 = W_hh + j2 * H + kt * 16;
        Af[kt][0] = pack_f16(r1[2 * c], r1[2 * c + 1]);
        Af[kt][1] = pack_f16(r2[2 * c], r2[2 * c + 1]);
        Af[kt][2] = pack_f16(r1[8 + 2 * c], r1[8 + 2 * c + 1]);
        Af[kt][3] = pack_f16(r2[8 + 2 * c], r2[8 + 2 * c + 1]);
    }
    // fp8: AW8 = e4m3(W) (for W*hlo term); AL8 = e4m3(Wlo*2048) (for Wlo*h term)
    uint32_t AW8[4][4], AL8[4][4];
#pragma unroll
    for (int q = 0; q < 4; ++q) {
        const int rows[2] = { j1, j2 };
#pragma unroll
        for (int half = 0; half < 2; ++half) {     // k offset 0 / 16
#pragma unroll
            for (int rr = 0; rr < 2; ++rr) {       // j1 / j2
                const float* p = W_hh + rows[rr] * H + q * 32 + half * 16 + 4 * c;
                float w0 = p[0], w1 = p[1], w2 = p[2], w3 = p[3];
                int reg = half * 2 + rr;           // a0=j1/k, a1=j2/k, a2=j1/k+16, a3=j2/k+16
                AW8[q][reg] = pack_e4m3_4(w0, w1, w2, w3);
                float l0 = (w0 - __half2float(__float2half_rn(w0))) * 2048.f;
                float l1 = (w1 - __half2float(__float2half_rn(w1))) * 2048.f;
                float l2 = (w2 - __half2float(__float2half_rn(w2))) * 2048.f;
                float l3 = (w3 - __half2float(__float2half_rn(w3))) * 2048.f;
                AL8[q][reg] = pack_e4m3_4(l0, l1, l2, l3);
            }
        }
    }

    const int lenA = lengths[b0 + mA];
    const int lenB = lengths[b0 + mB];

    // --- precomputed store/load offsets ------------------------------------
    const int rof = c * 8 + (g ^ c);              // shared read offset
    const int pp = g >> 1;
    const int mwA = w * 32 + pp * 8 + (mA ^ pp);  // main word (j1, mA)
    const int mwB = w * 32 + pp * 8 + (mB ^ pp);
    const int mby = (g & 1) * 2;                  // byte offset in word
    const int cwA = g >> 2, cwB = 2 + (g >> 2);
    const int fbase = (w & 1) * 128 + (w >> 1) * 32;
    const int fw1A = fbase + cwA * 8 + (mA ^ cwA);   // fp8 word (j1, mA)
    const int fw1B = fbase + cwA * 8 + (mB ^ cwA);
    const int fw2A = fbase + cwB * 8 + (mA ^ cwB);   // fp8 word (j2, mA)
    const int fw2B = fbase + cwB * 8 + (mB ^ cwB);
    const int fby = g & 3;

    __syncthreads();

    // --- store h into all three B tiles of buffer `s` ---
    auto store_all = [&](int s, float hA1, float hB1, float hA2, float hB2) {
        __half fA1 = __float2half_rn(hA1), fB1 = __float2half_rn(hB1);
        __half fA2 = __float2half_rn(hA2), fB2 = __float2half_rn(hB2);
        char* mn = (char*)(sm + MAIN_OFF(s));
        *(unsigned short*)(mn + mwA * 4 + mby)          = __half_as_ushort(fA1);
        *(unsigned short*)(mn + mwB * 4 + mby)          = __half_as_ushort(fB1);
        *(unsigned short*)(mn + (256 + mwA) * 4 + mby)  = __half_as_ushort(fA2);
        *(unsigned short*)(mn + (256 + mwB) * 4 + mby)  = __half_as_ushort(fB2);
        float lA1 = (hA1 - __half2float(fA1)) * 4096.f;
        float lB1 = (hB1 - __half2float(fB1)) * 4096.f;
        float lA2 = (hA2 - __half2float(fA2)) * 4096.f;
        float lB2 = (hB2 - __half2float(fB2)) * 4096.f;
        char* fl = (char*)(sm + FLO_OFF(s));
        uint16_t p1 = e4m3x2(lB1, lA1);
        fl[fw1A * 4 + fby] = (char)p1;
        fl[fw1B * 4 + fby] = (char)(p1 >> 8);
        uint16_t p2 = e4m3x2(lB2, lA2);
        fl[fw2A * 4 + fby] = (char)p2;
        fl[fw2B * 4 + fby] = (char)(p2 >> 8);
        char* fh = (char*)(sm + FH_OFF(s));
        uint16_t q1 = e4m3x2(hB1, hA1);
        fh[fw1A * 4 + fby] = (char)q1;
        fh[fw1B * 4 + fby] = (char)(q1 >> 8);
        uint16_t q2 = e4m3x2(hB2, hA2);
        fh[fw2A * 4 + fby] = (char)q2;
        fh[fw2B * 4 + fby] = (char)(q2 >> 8);
    };

    // --- peel step 0: h1 = tanh(proj[x_0]) ---
    {
        int tkA = Tok[mA * T], tkB = Tok[mB * T];
        float hA1 = fast_tanh(Ps[tkA * PSW + j1]);
        float hB1 = fast_tanh(Ps[tkB * PSW + j1]);
        float hA2 = fast_tanh(Ps[tkA * PSW + j2]);
        float hB2 = fast_tanh(Ps[tkB * PSW + j2]);
        if (lenA == 1) { Ls[mA * H + j1] = hA1; Ls[mA * H + j2] = hA2; }
        if (lenB == 1) { Ls[mB * H + j1] = hB1; Ls[mB * H + j2] = hB2; }
        store_all(0, hA1, hB1, hA2, hB2);
    }
    __syncthreads();

    for (int i = 1; i < T; ++i) {
        const int rs = (i - 1) & 1, ws = i & 1;
        const float* Mc = sm + MAIN_OFF(rs);
        const float* Lc = sm + FLO_OFF(rs);
        const float* Hc = sm + FH_OFF(rs);

        // prefetch token + proj adds (hidden under MMA)
        int tkA = Tok[mA * T + i], tkB = Tok[mB * T + i];
        float pA1 = Ps[tkA * PSW + j1];
        float pB1 = Ps[tkB * PSW + j1];
        float pA2 = Ps[tkA * PSW + j2];
        float pB2 = Ps[tkB * PSW + j2];

        float aM0[4] = {0.f, 0.f, 0.f, 0.f}, aM1[4] = {0.f, 0.f, 0.f, 0.f};
        float aA[4]  = {0.f, 0.f, 0.f, 0.f}, aB[4]  = {0.f, 0.f, 0.f, 0.f};

#pragma unroll
        for (int kt = 0; kt < 8; ++kt) {
            uint32_t b0v = __float_as_uint(Mc[kt * 32 + rof]);
            uint32_t b1v = __float_as_uint(Mc[256 + kt * 32 + rof]);
            mma_f16((kt & 1) ? aM1 : aM0, Af[kt], b0v, b1v);
        }
#pragma unroll
        for (int q = 0; q < 4; ++q) {
            uint32_t l0 = __float_as_uint(Lc[q * 32 + rof]);
            uint32_t l1 = __float_as_uint(Lc[128 + q * 32 + rof]);
            mma_fp8(aA, AW8[q], l0, l1);
            uint32_t h0 = __float_as_uint(Hc[q * 32 + rof]);
            uint32_t h1 = __float_as_uint(Hc[128 + q * 32 + rof]);
            mma_fp8(aB, AL8[q], h0, h1);
        }

        const float s1 = 1.f / 4096.f, s2 = 1.f / 2048.f;
        float z0 = (aM0[0] + aM1[0]) + aA[0] * s1 + aB[0] * s2 + pA1;
        float z1 = (aM0[1] + aM1[1]) + aA[1] * s1 + aB[1] * s2 + pB1;
        float z2 = (aM0[2] + aM1[2]) + aA[2] * s1 + aB[2] * s2 + pA2;
        float z3 = (aM0[3] + aM1[3]) + aA[3] * s1 + aB[3] * s2 + pB2;
        float hA1 = fast_tanh(z0), hB1 = fast_tanh(z1);
        float hA2 = fast_tanh(z2), hB2 = fast_tanh(z3);

        if (i == lenA - 1) { Ls[mA * H + j1] = hA1; Ls[mA * H + j2] = hA2; }
        if (i == lenB - 1) { Ls[mB * H + j1] = hB1; Ls[mB * H + j2] = hB2; }
        store_all(ws, hA1, hB1, hA2, hB2);
        __syncthreads();
    }

    // --- FC epilogue: out[b] = Ls[b] @ W_fc^T + b_fc (reuse Ps for W_fc) ---
    for (int idx = tid; idx < V * H; idx += NT) {
        int v = idx >> 7, j = idx & 127;
        Ps[v * PSW + j] = W_fc[idx];
    }
    __syncthreads();

    for (int p = tid; p < M * V; p += NT) {
        const int m = p / V, v = p % V;
        const float* lr = Ls + m * H;
        const float* wr = Ps + v * PSW;
        float s = b_fc[v];
#pragma unroll 8
        for (int k = 0; k < H; ++k) s += lr[k] * wr[k];
        out[(b0 + m) * V + v] = s;
    }
}

extern "C" void kernel_launch(void* const* d_in, const int* in_sizes, int n_in,
                              void* d_out, int out_size) {
    const int*   x       = (const int*)d_in[0];
    const int*   lengths = (const int*)d_in[1];
    const float* emb     = (const float*)d_in[2];
    const float* W_ih    = (const float*)d_in[3];
    const float* W_hh    = (const float*)d_in[4];
    const float* W_fc    = (const float*)d_in[5];
    const float* b_fc    = (const float*)d_in[6];
    float*       out     = (float*)d_out;

    proj_kernel<<<V, H>>>(emb, W_ih);

    size_t smem = (size_t)SMWORDS * sizeof(float);
    cudaFuncSetAttribute(rnn_kernel, cudaFuncAttributeMaxDynamicSharedMemorySize,
                         (int)smem);
    rnn_kernel<<<NCTA, NT, smem>>>(x, lengths, W_hh, W_fc, b_fc, out);
}